// round 1
// baseline (speedup 1.0000x reference)
#include <cuda_runtime.h>
#include <cstdint>

// GRU seq2seq: B=512, S=128(enc), P=32, F=O=64, H=1024, IN=128, 159 total steps.
// Strategy: fused per-step kernel (x|h concat-K GEMM + gating epilogue) using
// packed fma.rn.f32x2 (FFMA2) for 2x fp32 throughput on sm_103a.

#define B_    512
#define S_    128
#define P_    32
#define F_    64
#define O_    64
#define H_    1024
#define IN_   128
#define TTOT  159     // S + P - 1

#define BM 64
#define BN 64
#define BK 16

// ---------------- scratch (static device globals; no allocation) ------------
__device__ float g_x[TTOT][B_][IN_];    // packed inputs per step (~41.7 MB)
__device__ float g_h[2][B_][H_];        // ping-pong hidden state
__device__ float g_Wdt[H_][O_];         // Wd transposed [k][o]

// ---------------- f32x2 helpers --------------------------------------------
__device__ __forceinline__ unsigned long long pack2(float x, float y) {
    unsigned long long r;
    asm("mov.b64 %0, {%1, %2};" : "=l"(r) : "f"(x), "f"(y));
    return r;
}
__device__ __forceinline__ void ffma2(unsigned long long& d,
                                      unsigned long long a,
                                      unsigned long long b) {
    asm("fma.rn.f32x2 %0, %1, %2, %0;" : "+l"(d) : "l"(a), "l"(b));
}
__device__ __forceinline__ float2 unpack2(unsigned long long v) {
    float2 f;
    asm("mov.b64 {%0, %1}, %2;" : "=f"(f.x), "=f"(f.y) : "l"(v));
    return f;
}

__device__ __forceinline__ float sigf(float x)  { return 1.f / (1.f + __expf(-x)); }
__device__ __forceinline__ float tanhf_(float x){ return 1.f - 2.f / (1.f + __expf(2.f * x)); }

// ---------------- pack kernel ----------------------------------------------
// Fills: g_x feats part (all 159 steps), g_x labels part (first 128 steps),
// zeros g_h[0], transposes Wd -> g_Wdt.
__global__ void pack_kernel(const float* __restrict__ feats,
                            const float* __restrict__ labels,
                            const float* __restrict__ Wd) {
    long idx = (long)blockIdx.x * 256 + threadIdx.x;
    const long N1 = (long)TTOT * B_ * F_;   // 5,210,112
    const long N2 = (long)S_   * B_ * O_;   // 4,194,304
    const long N3 = (long)B_ * H_;          // 524,288
    const long N4 = (long)H_ * O_;          // 65,536
    if (idx < N1) {
        int t = (int)(idx / (B_ * F_));
        int r = (int)(idx % (B_ * F_));
        int b = r / F_, c = r % F_;
        g_x[t][b][c] = feats[((long)b * TTOT + t) * F_ + c];
        return;
    }
    idx -= N1;
    if (idx < N2) {
        int t = (int)(idx / (B_ * O_));
        int r = (int)(idx % (B_ * O_));
        int b = r / O_, c = r % O_;
        g_x[t][b][F_ + c] = labels[((long)b * S_ + t) * O_ + c];
        return;
    }
    idx -= N2;
    if (idx < N3) {
        ((float*)g_h)[idx] = 0.f;   // zero g_h[0]
        return;
    }
    idx -= N3;
    if (idx < N4) {
        int k = (int)(idx / O_), o = (int)(idx % O_);
        g_Wdt[k][o] = Wd[(long)o * H_ + k];
    }
}

// ---------------- fused GRU step: GEMM phase helper -------------------------
__device__ __forceinline__ void gemm_phase(
    const float* __restrict__ A, const float* __restrict__ W,
    int ld, int KC, int bm0, int bn0, int lm, int lk, int tx, int ty,
    float (*As)[BM + 4], float (*Bs)[BK][BN + 4],
    unsigned long long (&accR)[4][2],
    unsigned long long (&accZ)[4][2],
    unsigned long long (&accN)[4][2])
{
    for (int kt = 0; kt < KC; kt += BK) {
        // global loads (K-major, contiguous)
        float4 av  = *(const float4*)&A[(bm0 + lm) * ld + kt + lk];
        float4 bv0 = *(const float4*)&W[(0 * H_ + bn0 + lm) * ld + kt + lk];
        float4 bv1 = *(const float4*)&W[(1 * H_ + bn0 + lm) * ld + kt + lk];
        float4 bv2 = *(const float4*)&W[(2 * H_ + bn0 + lm) * ld + kt + lk];
        __syncthreads();
        As[lk + 0][lm] = av.x;  As[lk + 1][lm] = av.y;
        As[lk + 2][lm] = av.z;  As[lk + 3][lm] = av.w;
        Bs[0][lk + 0][lm] = bv0.x; Bs[0][lk + 1][lm] = bv0.y;
        Bs[0][lk + 2][lm] = bv0.z; Bs[0][lk + 3][lm] = bv0.w;
        Bs[1][lk + 0][lm] = bv1.x; Bs[1][lk + 1][lm] = bv1.y;
        Bs[1][lk + 2][lm] = bv1.z; Bs[1][lk + 3][lm] = bv1.w;
        Bs[2][lk + 0][lm] = bv2.x; Bs[2][lk + 1][lm] = bv2.y;
        Bs[2][lk + 2][lm] = bv2.z; Bs[2][lk + 3][lm] = bv2.w;
        __syncthreads();
        #pragma unroll
        for (int k = 0; k < BK; ++k) {
            float4 a4 = *(const float4*)&As[k][ty * 4];
            unsigned long long ap[4];
            ap[0] = pack2(a4.x, a4.x);
            ap[1] = pack2(a4.y, a4.y);
            ap[2] = pack2(a4.z, a4.z);
            ap[3] = pack2(a4.w, a4.w);
            const unsigned long long* bR =
                (const unsigned long long*)&Bs[0][k][tx * 4];
            const unsigned long long* bZ =
                (const unsigned long long*)&Bs[1][k][tx * 4];
            const unsigned long long* bN =
                (const unsigned long long*)&Bs[2][k][tx * 4];
            unsigned long long br0 = bR[0], br1 = bR[1];
            unsigned long long bz0 = bZ[0], bz1 = bZ[1];
            unsigned long long bn0_ = bN[0], bn1_ = bN[1];
            #pragma unroll
            for (int ii = 0; ii < 4; ++ii) {
                ffma2(accR[ii][0], ap[ii], br0);
                ffma2(accR[ii][1], ap[ii], br1);
                ffma2(accZ[ii][0], ap[ii], bz0);
                ffma2(accZ[ii][1], ap[ii], bz1);
                ffma2(accN[ii][0], ap[ii], bn0_);
                ffma2(accN[ii][1], ap[ii], bn1_);
            }
        }
    }
}

// ---------------- fused GRU step kernel ------------------------------------
__global__ __launch_bounds__(256)
void gru_step_kernel(int t, int cur,
                     const float* __restrict__ Wi, const float* __restrict__ Wh,
                     const float* __restrict__ bi, const float* __restrict__ bh)
{
    __shared__ float As[BK][BM + 4];
    __shared__ float Bs[3][BK][BN + 4];

    const int tid = threadIdx.x;
    const int tx = tid % 16;
    const int ty = tid / 16;
    const int lm = tid >> 2;          // 0..63  (row within tile for gmem load)
    const int lk = (tid & 3) * 4;     // 0,4,8,12
    const int bm0 = blockIdx.x * BM;  // batch offset
    const int bn0 = blockIdx.y * BN;  // hidden-col offset

    const float* h_in  = &g_h[cur][0][0];
    float*       h_out = &g_h[cur ^ 1][0][0];
    const float* xt    = &g_x[t][0][0];

    unsigned long long accR[4][2], accZ[4][2], accIN[4][2], accHN[4][2];
    #pragma unroll
    for (int i = 0; i < 4; ++i)
        #pragma unroll
        for (int j = 0; j < 2; ++j) {
            accR[i][j] = 0ULL; accZ[i][j] = 0ULL;
            accIN[i][j] = 0ULL; accHN[i][j] = 0ULL;
        }

    // phase 0: x part (K=128, Wi);  n-gate -> accIN
    gemm_phase(xt, Wi, IN_, IN_, bm0, bn0, lm, lk, tx, ty, As, Bs,
               accR, accZ, accIN);
    // phase 1: h part (K=1024, Wh); n-gate -> accHN
    gemm_phase(h_in, Wh, H_, H_, bm0, bn0, lm, lk, tx, ty, As, Bs,
               accR, accZ, accHN);

    // epilogue: gate + state update
    #pragma unroll
    for (int ii = 0; ii < 4; ++ii) {
        const int b = bm0 + ty * 4 + ii;
        #pragma unroll
        for (int jp = 0; jp < 2; ++jp) {
            float2 r2  = unpack2(accR[ii][jp]);
            float2 z2  = unpack2(accZ[ii][jp]);
            float2 in2 = unpack2(accIN[ii][jp]);
            float2 hn2 = unpack2(accHN[ii][jp]);
            #pragma unroll
            for (int u = 0; u < 2; ++u) {
                const int j = bn0 + tx * 4 + jp * 2 + u;
                float rs = (u == 0) ? r2.x  : r2.y;
                float zs = (u == 0) ? z2.x  : z2.y;
                float is = (u == 0) ? in2.x : in2.y;
                float hs = (u == 0) ? hn2.x : hn2.y;
                float rv = sigf(rs + bi[j] + bh[j]);
                float zv = sigf(zs + bi[H_ + j] + bh[H_ + j]);
                float hn = hs + bh[2 * H_ + j];
                float nv = tanhf_(is + bi[2 * H_ + j] + rv * hn);
                float ho = h_in[b * H_ + j];
                h_out[b * H_ + j] = nv + zv * (ho - nv);
            }
        }
    }
}

// ---------------- ps = h @ Wd.T + bd ---------------------------------------
// grid 128 blocks x 256 thr; block handles 4 batches x 64 outputs, K split 4.
// Writes out slab, and (optionally) the ps-half of the next decoder x slot.
__global__ __launch_bounds__(256)
void ps_kernel(int cur, const float* __restrict__ bd,
               float* __restrict__ out_slot, int xslot)
{
    __shared__ float hsm[4][H_];
    __shared__ float red[4][4][O_];   // [s][b][o]
    const int tid = threadIdx.x;
    const int o = tid % 64;
    const int s = tid / 64;
    const int b0 = blockIdx.x * 4;
    const float* h = &g_h[cur][0][0];

    for (int i = tid; i < 4 * H_; i += 256) {
        int bb = i / H_, k = i % H_;
        hsm[bb][k] = h[(b0 + bb) * H_ + k];
    }
    __syncthreads();

    float acc0 = 0.f, acc1 = 0.f, acc2 = 0.f, acc3 = 0.f;
    const int k0 = s * (H_ / 4);
    for (int k = k0; k < k0 + (H_ / 4); ++k) {
        float w = g_Wdt[k][o];
        acc0 += hsm[0][k] * w;
        acc1 += hsm[1][k] * w;
        acc2 += hsm[2][k] * w;
        acc3 += hsm[3][k] * w;
    }
    red[s][0][o] = acc0; red[s][1][o] = acc1;
    red[s][2][o] = acc2; red[s][3][o] = acc3;
    __syncthreads();

    if (s == 0) {
        #pragma unroll
        for (int bb = 0; bb < 4; ++bb) {
            float v = red[0][bb][o] + red[1][bb][o] +
                      red[2][bb][o] + red[3][bb][o] + bd[o];
            out_slot[(b0 + bb) * O_ + o] = v;
            if (xslot >= 0) g_x[xslot][b0 + bb][F_ + o] = v;
        }
    }
}

// ---------------- launch ----------------------------------------------------
extern "C" void kernel_launch(void* const* d_in, const int* in_sizes, int n_in,
                              void* d_out, int out_size)
{
    const float* feats  = (const float*)d_in[0];
    const float* labels = (const float*)d_in[1];
    const float* Wi     = (const float*)d_in[2];
    const float* Wh     = (const float*)d_in[3];
    const float* bi     = (const float*)d_in[4];
    const float* bh     = (const float*)d_in[5];
    const float* Wd     = (const float*)d_in[6];
    const float* bd     = (const float*)d_in[7];
    float* out = (float*)d_out;

    {
        const long total = (long)TTOT * B_ * F_ + (long)S_ * B_ * O_ +
                           (long)B_ * H_ + (long)H_ * O_;
        const int blocks = (int)((total + 255) / 256);
        pack_kernel<<<blocks, 256>>>(feats, labels, Wd);
    }

    dim3 grid(B_ / BM, H_ / BN);   // 8 x 16 = 128 CTAs
    int cur = 0;

    // encoder: 128 steps
    for (int t = 0; t < S_; ++t) {
        gru_step_kernel<<<grid, 256>>>(t, cur, Wi, Wh, bi, bh);
        cur ^= 1;
    }
    // first prediction -> out[0], and feed decoder x slot 128
    ps_kernel<<<B_ / 4, 256>>>(cur, bd, out, S_);

    // decoder: 31 steps
    for (int i = 0; i < P_ - 1; ++i) {
        gru_step_kernel<<<grid, 256>>>(S_ + i, cur, Wi, Wh, bi, bh);
        cur ^= 1;
        ps_kernel<<<B_ / 4, 256>>>(cur, bd,
                                   out + (long)(i + 1) * B_ * O_,
                                   (i < P_ - 2) ? (S_ + 1 + i) : -1);
    }
}